// round 9
// baseline (speedup 1.0000x reference)
#include <cuda_runtime.h>
#include <cstdint>

// Problem constants
#define T_TOK   512
#define H_DIM   2048
#define I_DIM   1024
#define N_EXP   16
#define K_TOP   4
#define N_PAIR  (T_TOK * K_TOP)
#define QBS     128

#define CTA_M   128
#define CTA_N   64
#define KI      64        // fp32 K per iteration
#define NTHR    256

// int8 quant: q in [-16128,16128], q = h*128 + l, h in [-126,126], l in [-64,63]
#define QMAX    16128.0f

// SMEM: row = 128B = [hi limb 64B | lo limb 64B]. A:128 rows, B:64 rows.
#define ATILE   16384     // 128 x 128B
#define BTILE   8192      // 64 x 128B
#define BUF_BYTES  (ATILE + BTILE)          // 24KB
#define SMEM_DYN   (2*BUF_BYTES + 256)      // double buffer ~48.25KB

// ---------------------------------------------------------------------------
// Scratch
// ---------------------------------------------------------------------------
__device__ int   g_off[N_EXP + 1];
__device__ int   g_pair[N_PAIR];
__device__ __align__(16) float g_hact[(N_PAIR + CTA_M) * I_DIM];
__device__ float g_amaxW0[16384];
__device__ float g_amaxW1[16384];
__device__ float g_amaxW2[32768];
__device__ float g_amaxX[512];
__device__ unsigned int g_amaxHbits[N_PAIR + 160];

// ---------------------------------------------------------------------------
// Helpers
// ---------------------------------------------------------------------------
__device__ __forceinline__ uint32_t smem_u32(const void* p) {
    uint32_t a;
    asm("{ .reg .u64 t; cvta.to.shared.u64 t, %1; cvt.u32.u64 %0, t; }" : "=r"(a) : "l"(p));
    return a;
}

__device__ __forceinline__ void ldsm_x4(uint32_t* r, uint32_t addr) {
    asm volatile("ldmatrix.sync.aligned.m8n8.x4.shared.b16 {%0,%1,%2,%3}, [%4];"
        : "=r"(r[0]), "=r"(r[1]), "=r"(r[2]), "=r"(r[3]) : "r"(addr));
}
__device__ __forceinline__ void ldsm_x2(uint32_t* r, uint32_t addr) {
    asm volatile("ldmatrix.sync.aligned.m8n8.x2.shared.b16 {%0,%1}, [%2];"
        : "=r"(r[0]), "=r"(r[1]) : "r"(addr));
}

__device__ __forceinline__ void imma16832(int* c, const uint32_t* a, const uint32_t* b) {
    asm volatile(
        "mma.sync.aligned.m16n8k32.row.col.s32.s8.s8.s32 "
        "{%0,%1,%2,%3}, {%4,%5,%6,%7}, {%8,%9}, {%0,%1,%2,%3};"
        : "+r"(c[0]), "+r"(c[1]), "+r"(c[2]), "+r"(c[3])
        : "r"(a[0]), "r"(a[1]), "r"(a[2]), "r"(a[3]), "r"(b[0]), "r"(b[1]));
}

__device__ __forceinline__ void sts16(uint32_t addr, uint32_t a, uint32_t b,
                                      uint32_t c, uint32_t d) {
    asm volatile("st.shared.v4.b32 [%0], {%1,%2,%3,%4};"
        :: "r"(addr), "r"(a), "r"(b), "r"(c), "r"(d) : "memory");
}

__device__ __forceinline__ uint32_t pack4(int a, int b, int c, int d) {
    return (uint32_t)(a & 255) | ((uint32_t)(b & 255) << 8)
         | ((uint32_t)(c & 255) << 16) | ((uint32_t)d << 24);
}

// fp32x4 * inv -> int15 -> (hi,lo) int8 limbs packed as u32 each
__device__ __forceinline__ void quant4(float4 v, float inv, uint32_t& hi, uint32_t& lo) {
    int q0 = __float2int_rn(v.x * inv);
    int q1 = __float2int_rn(v.y * inv);
    int q2 = __float2int_rn(v.z * inv);
    int q3 = __float2int_rn(v.w * inv);
    int h0 = (q0 + 64) >> 7, h1 = (q1 + 64) >> 7, h2 = (q2 + 64) >> 7, h3 = (q3 + 64) >> 7;
    int l0 = q0 - (h0 << 7), l1 = q1 - (h1 << 7), l2 = q2 - (h2 << 7), l3 = q3 - (h3 << 7);
    hi = pack4(h0, h1, h2, h3);
    lo = pack4(l0, l1, l2, l3);
}

__device__ __forceinline__ uint32_t swz(uint32_t base, uint32_t row, uint32_t chunk) {
    return base + row * 128u + ((chunk ^ (row & 7u)) << 4);
}

// ---------------------------------------------------------------------------
// Kernel P: per-row amax (weights incl. dequant scale; x raw)
// one warp per row, 8 warps/block
// ---------------------------------------------------------------------------
__global__ void prep_kernel(const float* __restrict__ w0, const float* __restrict__ w1,
                            const float* __restrict__ w2, const float* __restrict__ x,
                            const float* __restrict__ s0, const float* __restrict__ s1,
                            const float* __restrict__ s2)
{
    const int wid  = threadIdx.x >> 5;
    const int lane = threadIdx.x & 31;
    const int gid  = blockIdx.x * 8 + wid;

    const float4* p4;
    const float* srow = nullptr;
    int iters;
    float* outp;

    if (gid < 16384) {
        int e = gid >> 10, i = gid & 1023;
        p4 = (const float4*)(w0 + (size_t)gid * 2048);
        srow = s0 + (e * 8 + (i >> 7)) * 16;  iters = 16;  outp = &g_amaxW0[gid];
    } else if (gid < 32768) {
        int g2 = gid - 16384;
        int e = g2 >> 10, i = g2 & 1023;
        p4 = (const float4*)(w1 + (size_t)g2 * 2048);
        srow = s1 + (e * 8 + (i >> 7)) * 16;  iters = 16;  outp = &g_amaxW1[g2];
    } else if (gid < 65536) {
        int g2 = gid - 32768;
        int e = g2 >> 11, h = g2 & 2047;
        p4 = (const float4*)(w2 + (size_t)g2 * 1024);
        srow = s2 + (e * 16 + (h >> 7)) * 8;  iters = 8;  outp = &g_amaxW2[g2];
    } else if (gid < 66048) {
        int g2 = gid - 65536;
        p4 = (const float4*)(x + (size_t)g2 * 2048);
        srow = nullptr;  iters = 16;  outp = &g_amaxX[g2];
    } else return;

    float amax = 0.f;
    for (int j = 0; j < iters; j++) {
        float sc = srow ? srow[j] : 1.0f;
        float4 v = p4[j * 32 + lane];
        float m = fmaxf(fmaxf(fabsf(v.x), fabsf(v.y)), fmaxf(fabsf(v.z), fabsf(v.w)));
        amax = fmaxf(amax, m * sc);
    }
    #pragma unroll
    for (int o = 16; o; o >>= 1) amax = fmaxf(amax, __shfl_xor_sync(~0u, amax, o));
    if (lane == 0) *outp = amax;
}

// ---------------------------------------------------------------------------
// Kernel 0: routing + zero hact-amax
// ---------------------------------------------------------------------------
__global__ void route_kernel(const int* __restrict__ sel32)
{
    __shared__ int cnt[N_EXP];
    __shared__ int cur[N_EXP];
    __shared__ int is64;
    const int tid = threadIdx.x;

    for (int i = tid; i < N_PAIR + 160; i += NTHR) g_amaxHbits[i] = 0u;

    if (tid == 0) is64 = 1;
    if (tid < N_EXP) cnt[tid] = 0;
    __syncthreads();

    for (int p = tid; p < N_PAIR / 2; p += NTHR)
        if (sel32[2 * p + 1] != 0) atomicExch(&is64, 0);
    __syncthreads();

    const int stride = is64 ? 2 : 1;
    for (int p = tid; p < N_PAIR; p += NTHR)
        atomicAdd(&cnt[sel32[(size_t)p * stride] & 15], 1);
    __syncthreads();

    if (tid == 0) {
        int acc = 0;
        for (int e = 0; e < N_EXP; e++) { g_off[e] = acc; cur[e] = acc; acc += cnt[e]; }
        g_off[N_EXP] = acc;
    }
    __syncthreads();

    for (int p = tid; p < N_PAIR; p += NTHR) {
        int e = sel32[(size_t)p * stride] & 15;
        g_pair[atomicAdd(&cur[e], 1)] = p;
    }
}

// ---------------------------------------------------------------------------
// Kernel 1: up-projection (int8 limb-split IMMA). CTA 128 x 64(interleaved g|u).
// ---------------------------------------------------------------------------
__global__ __launch_bounds__(NTHR, 1)
void gemm1_kernel(const float* __restrict__ x,  const float* __restrict__ w0,
                  const float* __restrict__ w1, const float* __restrict__ s0,
                  const float* __restrict__ s1)
{
    const int e    = blockIdx.y;
    const int base = g_off[e];
    const int cntE = g_off[e + 1] - base;
    const int m0   = blockIdx.z * CTA_M;
    if (m0 >= cntE) return;
    const int i0   = blockIdx.x * 32;

    extern __shared__ char dsm[];
    __shared__ int srow[CTA_M];
    const uint32_t sb = (smem_u32(dsm) + 127u) & ~127u;

    const int tid  = threadIdx.x;
    const int wid  = tid >> 5;
    const int lane = tid & 31;

    if (tid < CTA_M) {
        int mm = m0 + tid;
        srow[tid] = (mm < cntE) ? (g_pair[base + mm] / K_TOP) : 0;
    }
    __syncthreads();

    // A loader: 2 threads/row (32 f32 each)
    const int rbA = tid >> 1;
    const int khA = (tid & 1) * 32;
    const int tokA = srow[rbA];
    const float* aSrc = x + (size_t)tokA * H_DIM + khA;
    {   // row amax (guard 0)
    }
    const float amx = g_amaxX[tokA];
    const float invA = (amx > 0.f) ? (QMAX / amx) : 0.f;

    // B loader: 4 threads/row (16 f32 each); rows interleave w0/w1
    const int rbB = tid >> 2;
    const int khB = (tid & 3) * 16;
    const int irow = i0 + (rbB >> 1);
    const float* bSrc = (rbB & 1)
        ? w1 + ((size_t)(e * I_DIM + irow)) * H_DIM + khB
        : w0 + ((size_t)(e * I_DIM + irow)) * H_DIM + khB;
    const float* sRow = ((rbB & 1) ? s1 : s0)
        + (size_t)(e * (I_DIM / QBS) + (i0 >> 7)) * (H_DIM / QBS);
    const float amB = (rbB & 1) ? g_amaxW1[e * I_DIM + irow] : g_amaxW0[e * I_DIM + irow];
    const float invB = (amB > 0.f) ? (QMAX / amB) : 0.f;

    // compute mapping: 4 M-warps x 2 N-warps
    const int wm = wid & 3, wn = wid >> 2;
    const int mW = wm * 32, nW = wn * 32;
    const int arow = lane & 15;
    const int ahalf = lane >> 4;
    const int brow = lane & 7;
    const int bhalf = (lane >> 3) & 1;

    int accHi[2][4][4], accMid[2][4][4];
    #pragma unroll
    for (int a = 0; a < 2; a++)
        #pragma unroll
        for (int b = 0; b < 4; b++)
            #pragma unroll
            for (int c = 0; c < 4; c++) { accHi[a][b][c] = 0; accMid[a][b][c] = 0; }

    const int NIT = H_DIM / KI;   // 32
    float4 aReg[8], bReg[4];

    const uint32_t cA0 = (uint32_t)((tid & 1) * 2);   // A hi chunks cA0, cA0+1
    const uint32_t cB0 = (uint32_t)(tid & 3);         // B hi chunk

    // prologue: iter 0 -> buf 0
    {
        const float4* ap = (const float4*)aSrc;
        const float4* bp = (const float4*)bSrc;
        #pragma unroll
        for (int q = 0; q < 8; q++) aReg[q] = ap[q];
        #pragma unroll
        for (int q = 0; q < 4; q++) bReg[q] = bp[q];
        const float scv = sRow[0] * invB;
        uint32_t hi[8], lo[8];
        #pragma unroll
        for (int q = 0; q < 8; q++) quant4(aReg[q], invA, hi[q], lo[q]);
        sts16(swz(sb, rbA, cA0),     hi[0], hi[1], hi[2], hi[3]);
        sts16(swz(sb, rbA, cA0 + 1), hi[4], hi[5], hi[6], hi[7]);
        sts16(swz(sb, rbA, cA0 + 4), lo[0], lo[1], lo[2], lo[3]);
        sts16(swz(sb, rbA, cA0 + 5), lo[4], lo[5], lo[6], lo[7]);
        #pragma unroll
        for (int q = 0; q < 4; q++) quant4(bReg[q], scv, hi[q], lo[q]);
        sts16(swz(sb + ATILE, rbB, cB0),     hi[0], hi[1], hi[2], hi[3]);
        sts16(swz(sb + ATILE, rbB, cB0 + 4), lo[0], lo[1], lo[2], lo[3]);
    }
    __syncthreads();

    for (int it = 0; it < NIT; it++) {
        if (it + 1 < NIT) {
            const float4* ap = (const float4*)(aSrc + (it + 1) * KI);
            const float4* bp = (const float4*)(bSrc + (it + 1) * KI);
            #pragma unroll
            for (int q = 0; q < 8; q++) aReg[q] = ap[q];
            #pragma unroll
            for (int q = 0; q < 4; q++) bReg[q] = bp[q];
        }

        const uint32_t bufA = sb + (uint32_t)(it & 1) * BUF_BYTES;
        const uint32_t bufB = bufA + ATILE;

        #pragma unroll
        for (int ks = 0; ks < 2; ks++) {
            uint32_t aH[2][4], aL[2][4], bH[4][2], bL[4][2];
            #pragma unroll
            for (int mf = 0; mf < 2; mf++) {
                uint32_t row = (uint32_t)(mW + mf * 16 + arow);
                uint32_t ch  = (uint32_t)(ks * 2 + ahalf);
                ldsm_x4(aH[mf], swz(bufA, row, ch));
                ldsm_x4(aL[mf], swz(bufA, row, ch + 4));
            }
            #pragma unroll
            for (int nf = 0; nf < 4; nf++) {
                uint32_t row = (uint32_t)(nW + nf * 8 + brow);
                uint32_t ch  = (uint32_t)(ks * 2 + bhalf);
                ldsm_x2(bH[nf], swz(bufB, row, ch));
                ldsm_x2(bL[nf], swz(bufB, row, ch + 4));
            }
            #pragma unroll
            for (int mf = 0; mf < 2; mf++)
                #pragma unroll
                for (int nf = 0; nf < 4; nf++) {
                    imma16832(accHi[mf][nf],  aH[mf], bH[nf]);
                    imma16832(accMid[mf][nf], aH[mf], bL[nf]);
                    imma16832(accMid[mf][nf], aL[mf], bH[nf]);
                }
        }

        if (it + 1 < NIT) {
            const uint32_t nbA = sb + (uint32_t)((it + 1) & 1) * BUF_BYTES;
            const uint32_t nbB = nbA + ATILE;
            const float scv = sRow[(it + 1) >> 1] * invB;
            uint32_t hi[8], lo[8];
            #pragma unroll
            for (int q = 0; q < 8; q++) quant4(aReg[q], invA, hi[q], lo[q]);
            sts16(swz(nbA, rbA, cA0),     hi[0], hi[1], hi[2], hi[3]);
            sts16(swz(nbA, rbA, cA0 + 1), hi[4], hi[5], hi[6], hi[7]);
            sts16(swz(nbA, rbA, cA0 + 4), lo[0], lo[1], lo[2], lo[3]);
            sts16(swz(nbA, rbA, cA0 + 5), lo[4], lo[5], lo[6], lo[7]);
            #pragma unroll
            for (int q = 0; q < 4; q++) quant4(bReg[q], scv, hi[q], lo[q]);
            sts16(swz(nbB, rbB, cB0),     hi[0], hi[1], hi[2], hi[3]);
            sts16(swz(nbB, rbB, cB0 + 4), lo[0], lo[1], lo[2], lo[3]);
        }
        __syncthreads();
    }

    // epilogue: rescale, silu(g)*u -> g_hact, per-row amax via atomicMax
    const float K1 = 128.0f / (QMAX * QMAX);
    const int qrow = lane >> 2;
    const int qcol = lane & 3;
    #pragma unroll
    for (int mf = 0; mf < 2; mf++) {
        const int r0 = mW + mf * 16 + qrow;
        const int r1 = r0 + 8;
        const bool v0 = (m0 + r0) < cntE;
        const bool v1 = (m0 + r1) < cntE;
        const float aX0 = g_amaxX[srow[r0]] * K1;
        const float aX1 = g_amaxX[srow[r1]] * K1;
        float rmax0 = 0.f, rmax1 = 0.f;
        #pragma unroll
        for (int nf = 0; nf < 4; nf++) {
            const int ii = i0 + wn * 16 + nf * 4 + qcol;
            const float aw0 = g_amaxW0[e * I_DIM + ii];
            const float aw1 = g_amaxW1[e * I_DIM + ii];
            {
                float gv = fmaf((float)accHi[mf][nf][0], 128.f, (float)accMid[mf][nf][0]) * (aX0 * aw0);
                float uv = fmaf((float)accHi[mf][nf][1], 128.f, (float)accMid[mf][nf][1]) * (aX0 * aw1);
                float h = gv / (1.0f + __expf(-gv)) * uv;
                if (v0) g_hact[(size_t)(base + m0 + r0) * I_DIM + ii] = h;
                rmax0 = fmaxf(rmax0, fabsf(h));
            }
            {
                float gv = fmaf((float)accHi[mf][nf][2], 128.f, (float)accMid[mf][nf][2]) * (aX1 * aw0);
                float uv = fmaf((float)accHi[mf][nf][3], 128.f, (float)accMid[mf][nf][3]) * (aX1 * aw1);
                float h = gv / (1.0f + __expf(-gv)) * uv;
                if (v1) g_hact[(size_t)(base + m0 + r1) * I_DIM + ii] = h;
                rmax1 = fmaxf(rmax1, fabsf(h));
            }
        }
        // reduce over qcol lanes (same rows)
        #pragma unroll
        for (int o = 1; o <= 2; o <<= 1) {
            rmax0 = fmaxf(rmax0, __shfl_xor_sync(~0u, rmax0, o));
            rmax1 = fmaxf(rmax1, __shfl_xor_sync(~0u, rmax1, o));
        }
        if (qcol == 0) {
            if (v0) atomicMax(&g_amaxHbits[base + m0 + r0], __float_as_uint(rmax0));
            if (v1) atomicMax(&g_amaxHbits[base + m0 + r1], __float_as_uint(rmax1));
        }
    }
}

// ---------------------------------------------------------------------------
// Kernel 2: down-projection (int8 limb-split IMMA) + routing weight scatter.
// ---------------------------------------------------------------------------
__global__ __launch_bounds__(NTHR, 1)
void gemm2_kernel(const float* __restrict__ w2, const float* __restrict__ s2,
                  const float* __restrict__ rw, float* __restrict__ out)
{
    const int e    = blockIdx.y;
    const int base = g_off[e];
    const int cntE = g_off[e + 1] - base;
    const int m0   = blockIdx.z * CTA_M;
    if (m0 >= cntE) return;
    const int n0   = blockIdx.x * CTA_N;

    extern __shared__ char dsm[];
    __shared__ int spair[CTA_M];
    const uint32_t sb = (smem_u32(dsm) + 127u) & ~127u;

    const int tid  = threadIdx.x;
    const int wid  = tid >> 5;
    const int lane = tid & 31;

    if (tid < CTA_M) {
        int mm = m0 + tid;
        spair[tid] = (mm < cntE) ? g_pair[base + mm] : 0;
    }
    __syncthreads();

    const int rbA = tid >> 1;
    const int khA = (tid & 1) * 32;
    const int rowA = base + m0 + rbA;
    const float* aSrc = g_hact + (size_t)rowA * I_DIM + khA;
    const float amA = __uint_as_float(g_amaxHbits[rowA]);
    const float invA = (amA > 0.f) ? (QMAX / amA) : 0.f;

    const int rbB = tid >> 2;
    const int khB = (tid & 3) * 16;
    const float* bSrc = w2 + ((size_t)(e * H_DIM + n0 + rbB)) * I_DIM + khB;
    const float* sRow = s2 + (size_t)(e * (H_DIM / QBS) + (n0 >> 7)) * (I_DIM / QBS);
    const float amB = g_amaxW2[e * H_DIM + n0 + rbB];
    const float invB = (amB > 0.f) ? (QMAX / amB) : 0.f;

    const int wm = wid & 3, wn = wid >> 2;
    const int mW = wm * 32, nW = wn * 32;
    const int arow = lane & 15;
    const int ahalf = lane >> 4;
    const int brow = lane & 7;
    const int bhalf = (lane >> 3) & 1;

    int accHi[2][4][4], accMid[2][4][4];
    #pragma unroll
    for (int a = 0; a < 2; a++)
        #pragma unroll
        for (int b = 0; b < 4; b++)
            #pragma unroll
            for (int c = 0; c < 4; c++) { accHi[a][b][c] = 0; accMid[a][b][c] = 0; }

    const int NIT = I_DIM / KI;   // 16
    float4 aReg[8], bReg[4];

    const uint32_t cA0 = (uint32_t)((tid & 1) * 2);
    const uint32_t cB0 = (uint32_t)(tid & 3);

    {
        const float4* ap = (const float4*)aSrc;
        const float4* bp = (const float4*)bSrc;
        #pragma unroll
        for (int q = 0; q < 8; q++) aReg[q] = ap[q];
        #pragma unroll
        for (int q = 0; q < 4; q++) bReg[q] = bp[q];
        const float scv = sRow[0] * invB;
        uint32_t hi[8], lo[8];
        #pragma unroll
        for (int q = 0; q < 8; q++) quant4(aReg[q], invA, hi[q], lo[q]);
        sts16(swz(sb, rbA, cA0),     hi[0], hi[1], hi[2], hi[3]);
        sts16(swz(sb, rbA, cA0 + 1), hi[4], hi[5], hi[6], hi[7]);
        sts16(swz(sb, rbA, cA0 + 4), lo[0], lo[1], lo[2], lo[3]);
        sts16(swz(sb, rbA, cA0 + 5), lo[4], lo[5], lo[6], lo[7]);
        #pragma unroll
        for (int q = 0; q < 4; q++) quant4(bReg[q], scv, hi[q], lo[q]);
        sts16(swz(sb + ATILE, rbB, cB0),     hi[0], hi[1], hi[2], hi[3]);
        sts16(swz(sb + ATILE, rbB, cB0 + 4), lo[0], lo[1], lo[2], lo[3]);
    }
    __syncthreads();

    for (int it = 0; it < NIT; it++) {
        if (it + 1 < NIT) {
            const float4* ap = (const float4*)(aSrc + (it + 1) * KI);
            const float4* bp = (const float4*)(bSrc + (it + 1) * KI);
            #pragma unroll
            for (int q = 0; q < 8; q++) aReg[q] = ap[q];
            #pragma unroll
            for (int q = 0; q < 4; q++) bReg[q] = bp[q];
        }

        const uint32_t bufA = sb + (uint32_t)(it & 1) * BUF_BYTES;
        const uint32_t bufB = bufA + ATILE;

        #pragma unroll
        for (int ks = 0; ks < 2; ks++) {
            uint32_t aH[2][4], aL[2][4], bH[4][2], bL[4][2];
            #pragma unroll
            for (int mf = 0; mf < 2; mf++) {
                uint32_t row = (uint32_t)(mW + mf * 16 + arow);
                uint32_t ch  = (uint32_t)(ks * 2 + ahalf);
                ldsm_x4(aH[mf], swz(bufA, row, ch));
                ldsm_x4(aL[mf], swz(bufA, row, ch + 4));
            }
            #pragma unroll
            for (int nf = 0; nf < 4; nf++) {
                uint32_t row = (uint32_t)(nW + nf * 8 + brow);
                uint32_t ch  = (uint32_t)(ks * 2 + bhalf);
                ldsm_x2(bH[nf], swz(bufB, row, ch));
                ldsm_x2(bL[nf], swz(bufB, row, ch + 4));
            }
            #pragma unroll
            for (int mf = 0; mf < 2; mf++)
                #pragma unroll
                for (int nf = 0; nf < 4; nf++) {
                    imma16832(accHi[mf][nf],  aH[mf], bH[nf]);
                    imma16832(accMid[mf][nf], aH[mf], bL[nf]);
                    imma16832(accMid[mf][nf], aL[mf], bH[nf]);
                }
        }

        if (it + 1 < NIT) {
            const uint32_t nbA = sb + (uint32_t)((it + 1) & 1) * BUF_BYTES;
            const uint32_t nbB = nbA + ATILE;
            const float scv = sRow[(it + 1) >> 1] * invB;
            uint32_t hi[8], lo[8];
            #pragma unroll
            for (int q = 0; q < 8; q++) quant4(aReg[q], invA, hi[q], lo[q]);
            sts16(swz(nbA, rbA, cA0),     hi[0], hi[1], hi[2], hi[3]);
            sts16(swz(nbA, rbA, cA0 + 1), hi[4], hi[5], hi[6], hi[7]);
            sts16(swz(nbA, rbA, cA0 + 4), lo[0], lo[1], lo[2], lo[3]);
            sts16(swz(nbA, rbA, cA0 + 5), lo[4], lo[5], lo[6], lo[7]);
            #pragma unroll
            for (int q = 0; q < 4; q++) quant4(bReg[q], scv, hi[q], lo[q]);
            sts16(swz(nbB, rbB, cB0),     hi[0], hi[1], hi[2], hi[3]);
            sts16(swz(nbB, rbB, cB0 + 4), lo[0], lo[1], lo[2], lo[3]);
        }
        __syncthreads();
    }

    // epilogue
    const float K1 = 128.0f / (QMAX * QMAX);
    const int qrow = lane >> 2;
    const int qcol = lane & 3;
    #pragma unroll
    for (int mf = 0; mf < 2; mf++) {
        const int r0 = mW + mf * 16 + qrow;
        const int r1 = r0 + 8;
        const bool v0 = (m0 + r0) < cntE;
        const bool v1 = (m0 + r1) < cntE;
        const int pid0 = spair[r0];
        const int pid1 = spair[r1];
        const float cA0f = __uint_as_float(g_amaxHbits[base + m0 + r0]) * K1 * rw[pid0];
        const float cA1f = __uint_as_float(g_amaxHbits[base + m0 + r1]) * K1 * rw[pid1];
        #pragma unroll
        for (int nf = 0; nf < 4; nf++) {
            const int col = n0 + nW + nf * 8 + qcol * 2;
            const float cb0 = g_amaxW2[e * H_DIM + col];
            const float cb1 = g_amaxW2[e * H_DIM + col + 1];
            if (v0) {
                float2 v;
                v.x = fmaf((float)accHi[mf][nf][0], 128.f, (float)accMid[mf][nf][0]) * (cA0f * cb0);
                v.y = fmaf((float)accHi[mf][nf][1], 128.f, (float)accMid[mf][nf][1]) * (cA0f * cb1);
                *(float2*)&out[(size_t)pid0 * H_DIM + col] = v;
            }
            if (v1) {
                float2 v;
                v.x = fmaf((float)accHi[mf][nf][2], 128.f, (float)accMid[mf][nf][2]) * (cA1f * cb0);
                v.y = fmaf((float)accHi[mf][nf][3], 128.f, (float)accMid[mf][nf][3]) * (cA1f * cb1);
                *(float2*)&out[(size_t)pid1 * H_DIM + col] = v;
            }
        }
    }
}

// ---------------------------------------------------------------------------
// Launch
// ---------------------------------------------------------------------------
extern "C" void kernel_launch(void* const* d_in, const int* in_sizes, int n_in,
                              void* d_out, int out_size)
{
    const float* x   = (const float*)d_in[0];
    const float* w0  = (const float*)d_in[1];
    const float* w1  = (const float*)d_in[2];
    const float* w2  = (const float*)d_in[3];
    const float* s0  = (const float*)d_in[4];
    const float* s1  = (const float*)d_in[5];
    const float* s2  = (const float*)d_in[6];
    const int*   sel = (const int*)  d_in[7];
    const float* rw  = (const float*)d_in[8];
    float*       out = (float*)d_out;

    cudaFuncSetAttribute(gemm1_kernel, cudaFuncAttributeMaxDynamicSharedMemorySize, SMEM_DYN);
    cudaFuncSetAttribute(gemm2_kernel, cudaFuncAttributeMaxDynamicSharedMemorySize, SMEM_DYN);

    prep_kernel<<<8256, NTHR>>>(w0, w1, w2, x, s0, s1, s2);
    route_kernel<<<1, NTHR>>>(sel);

    dim3 g1(I_DIM / 32, N_EXP, N_PAIR / CTA_M);    // 32 x 16 x 16 (z early-exits)
    gemm1_kernel<<<g1, NTHR, SMEM_DYN>>>(x, w0, w1, s0, s1);

    dim3 g2(H_DIM / CTA_N, N_EXP, N_PAIR / CTA_M); // 32 x 16 x 16
    gemm2_kernel<<<g2, NTHR, SMEM_DYN>>>(w2, s2, rw, out);
}

// round 10
// speedup vs baseline: 1.8313x; 1.8313x over previous
#include <cuda_runtime.h>
#include <cuda_bf16.h>
#include <cstdint>

// Problem constants
#define T_TOK   512
#define H_DIM   2048
#define I_DIM   1024
#define N_EXP   16
#define K_TOP   4
#define N_PAIR  (T_TOK * K_TOP)
#define QBS     128

#define CTA_M   128
#define CTA_N   64
#define KI      64        // fp32 K per iteration
#define NTHR    256

// SMEM blocks: rows x 128B (KI=64 bf16). A:128 rows, B:64 rows. hi+lo each.
#define ABLK    16384     // 128 x 128B
#define BBLK    8192      // 64 x 128B
#define BUF_BYTES  (2*ABLK + 2*BBLK)        // 48KB
#define SMEM_DYN   (2*BUF_BYTES + 256)      // double buffer -> ~96.25KB

// ---------------------------------------------------------------------------
// Scratch
// ---------------------------------------------------------------------------
__device__ int   g_off[N_EXP + 1];
__device__ int   g_pair[N_PAIR];
__device__ __align__(16) float g_hact[(N_PAIR + CTA_M) * I_DIM];

// ---------------------------------------------------------------------------
// Helpers
// ---------------------------------------------------------------------------
__device__ __forceinline__ uint32_t smem_u32(const void* p) {
    uint32_t a;
    asm("{ .reg .u64 t; cvta.to.shared.u64 t, %1; cvt.u32.u64 %0, t; }" : "=r"(a) : "l"(p));
    return a;
}

__device__ __forceinline__ void ldsm_x4(uint32_t* r, uint32_t addr) {
    asm volatile("ldmatrix.sync.aligned.m8n8.x4.shared.b16 {%0,%1,%2,%3}, [%4];"
        : "=r"(r[0]), "=r"(r[1]), "=r"(r[2]), "=r"(r[3]) : "r"(addr));
}
__device__ __forceinline__ void ldsm_x2(uint32_t* r, uint32_t addr) {
    asm volatile("ldmatrix.sync.aligned.m8n8.x2.shared.b16 {%0,%1}, [%2];"
        : "=r"(r[0]), "=r"(r[1]) : "r"(addr));
}

__device__ __forceinline__ void mma16816(float* c, const uint32_t* a, const uint32_t* b) {
    asm volatile(
        "mma.sync.aligned.m16n8k16.row.col.f32.bf16.bf16.f32 "
        "{%0,%1,%2,%3}, {%4,%5,%6,%7}, {%8,%9}, {%0,%1,%2,%3};"
        : "+f"(c[0]), "+f"(c[1]), "+f"(c[2]), "+f"(c[3])
        : "r"(a[0]), "r"(a[1]), "r"(a[2]), "r"(a[3]), "r"(b[0]), "r"(b[1]));
}

__device__ __forceinline__ void sts8(uint32_t addr, uint32_t v0, uint32_t v1) {
    asm volatile("st.shared.v2.b32 [%0], {%1,%2};" :: "r"(addr), "r"(v0), "r"(v1) : "memory");
}

// fp32x4 -> bf16 hi/lo, 8B to hi block + 8B to lo block; 128B-row XOR swizzle.
__device__ __forceinline__ void cvt_store(float4 v, int rb, int k0,
                                          uint32_t baseHi, uint32_t baseLo) {
    uint32_t chunk = (uint32_t)(k0 >> 3);
    uint32_t phys  = (uint32_t)rb * 128u + ((chunk ^ ((uint32_t)rb & 7u)) << 4) + ((k0 & 4) << 1);
    __nv_bfloat162 h0 = __floats2bfloat162_rn(v.x, v.y);
    __nv_bfloat162 h1 = __floats2bfloat162_rn(v.z, v.w);
    float rx = v.x - __bfloat162float(h0.x);
    float ry = v.y - __bfloat162float(h0.y);
    float rz = v.z - __bfloat162float(h1.x);
    float rw = v.w - __bfloat162float(h1.y);
    __nv_bfloat162 l0 = __floats2bfloat162_rn(rx, ry);
    __nv_bfloat162 l1 = __floats2bfloat162_rn(rz, rw);
    sts8(baseHi + phys, *(uint32_t*)&h0, *(uint32_t*)&h1);
    sts8(baseLo + phys, *(uint32_t*)&l0, *(uint32_t*)&l1);
}

// ---------------------------------------------------------------------------
// Kernel 0: routing (robust to int32/int64 selected_experts)
// ---------------------------------------------------------------------------
__global__ void route_kernel(const int* __restrict__ sel32)
{
    __shared__ int cnt[N_EXP];
    __shared__ int cur[N_EXP];
    __shared__ int is64;
    const int tid = threadIdx.x;

    if (tid == 0) is64 = 1;
    if (tid < N_EXP) cnt[tid] = 0;
    __syncthreads();

    for (int p = tid; p < N_PAIR / 2; p += NTHR)
        if (sel32[2 * p + 1] != 0) atomicExch(&is64, 0);
    __syncthreads();

    const int stride = is64 ? 2 : 1;
    for (int p = tid; p < N_PAIR; p += NTHR)
        atomicAdd(&cnt[sel32[(size_t)p * stride] & 15], 1);
    __syncthreads();

    if (tid == 0) {
        int acc = 0;
        for (int e = 0; e < N_EXP; e++) { g_off[e] = acc; cur[e] = acc; acc += cnt[e]; }
        g_off[N_EXP] = acc;
    }
    __syncthreads();

    for (int p = tid; p < N_PAIR; p += NTHR) {
        int e = sel32[(size_t)p * stride] & 15;
        g_pair[atomicAdd(&cur[e], 1)] = p;
    }
}

// ---------------------------------------------------------------------------
// Kernel 1: up-projection (bf16-split mma.sync). CTA 128 x 64.
// B rows interleave w0/w1: row r -> (r&1 ? w1 : w0) row (i0 + r/2);
// acc col pair (2j,2j+1) = (g_i, u_i). Epilogue: silu(g)*u -> g_hact.
// Tail M-tiles skip MMA fragments beyond mRows (16-row granularity).
// ---------------------------------------------------------------------------
__global__ __launch_bounds__(NTHR, 2)
void gemm1_kernel(const float* __restrict__ x,  const float* __restrict__ w0,
                  const float* __restrict__ w1, const float* __restrict__ s0,
                  const float* __restrict__ s1)
{
    const int e    = blockIdx.y;
    const int base = g_off[e];
    const int cntE = g_off[e + 1] - base;
    const int m0   = blockIdx.z * CTA_M;
    if (m0 >= cntE) return;
    const int mRows = min(CTA_M, cntE - m0);
    const int i0   = blockIdx.x * 32;      // 32 i per CTA (64 interleaved rows)

    extern __shared__ char dsm[];
    __shared__ int srow[CTA_M];
    const uint32_t sb = (smem_u32(dsm) + 127u) & ~127u;

    const int tid  = threadIdx.x;
    const int wid  = tid >> 5;
    const int lane = tid & 31;

    if (tid < CTA_M) {
        int mm = m0 + tid;
        srow[tid] = (mm < cntE) ? (g_pair[base + mm] / K_TOP) : 0;
    }
    __syncthreads();

    // A loader: 2 threads/row, 32 f32 each
    const int rbA = tid >> 1;
    const int khA = (tid & 1) * 32;
    const float* aSrc = x + (size_t)srow[rbA] * H_DIM + khA;
    // B loader: 4 threads/row, 16 f32 each
    const int rbB = tid >> 2;
    const int khB = (tid & 3) * 16;
    const int irow = i0 + (rbB >> 1);
    const float* bSrc = (rbB & 1)
        ? w1 + ((size_t)(e * I_DIM + irow)) * H_DIM + khB
        : w0 + ((size_t)(e * I_DIM + irow)) * H_DIM + khB;
    const float* sRow = ((rbB & 1) ? s1 : s0)
        + (size_t)(e * (I_DIM / QBS) + (i0 >> 7)) * (H_DIM / QBS);

    // compute mapping: 4 M-warps x 2 N-warps
    const int wm = wid & 3, wn = wid >> 2;
    const int mW = wm * 32, nW = wn * 32;
    const int arow = lane & 15;
    const int ahalf = lane >> 4;
    const int brow = lane & 7;
    const int bhalf = (lane >> 3) & 1;

    // active M-fragments for this warp (skip padding rows)
    const int nMf = (mW < mRows) ? ((mW + 16 < mRows) ? 2 : 1) : 0;

    float acc[2][4][4];
    #pragma unroll
    for (int a = 0; a < 2; a++)
        #pragma unroll
        for (int b = 0; b < 4; b++)
            #pragma unroll
            for (int c = 0; c < 4; c++) acc[a][b][c] = 0.f;

    const int NIT = H_DIM / KI;   // 32
    float4 aReg[8], bReg[4];

    // prologue: iter 0 -> buf 0
    {
        const float4* ap = (const float4*)aSrc;
        const float4* bp = (const float4*)bSrc;
        #pragma unroll
        for (int q = 0; q < 8; q++) aReg[q] = ap[q];
        #pragma unroll
        for (int q = 0; q < 4; q++) bReg[q] = bp[q];
        const float sc = sRow[0];
        #pragma unroll
        for (int q = 0; q < 8; q++)
            cvt_store(aReg[q], rbA, khA + q * 4, sb, sb + ABLK);
        #pragma unroll
        for (int q = 0; q < 4; q++) {
            float4 vb = bReg[q];
            vb.x *= sc; vb.y *= sc; vb.z *= sc; vb.w *= sc;
            cvt_store(vb, rbB, khB + q * 4, sb + 2 * ABLK, sb + 2 * ABLK + BBLK);
        }
    }
    __syncthreads();

    for (int it = 0; it < NIT; it++) {
        if (it + 1 < NIT) {
            const float4* ap = (const float4*)(aSrc + (it + 1) * KI);
            const float4* bp = (const float4*)(bSrc + (it + 1) * KI);
            #pragma unroll
            for (int q = 0; q < 8; q++) aReg[q] = ap[q];
            #pragma unroll
            for (int q = 0; q < 4; q++) bReg[q] = bp[q];
        }

        const uint32_t bufB = sb + (uint32_t)(it & 1) * BUF_BYTES;
        const uint32_t sbAhi = bufB, sbAlo = bufB + ABLK;
        const uint32_t sbBhi = bufB + 2 * ABLK, sbBlo = sbBhi + BBLK;

        #pragma unroll
        for (int ks = 0; ks < 4; ks++) {
            uint32_t aH[2][4], aL[2][4], bH[4][2], bL[4][2];
            #pragma unroll
            for (int mf = 0; mf < 2; mf++) if (mf < nMf) {
                uint32_t row = (uint32_t)(mW + mf * 16 + arow);
                uint32_t off = row * 128u + ((((uint32_t)(ks * 2 + ahalf)) ^ (row & 7u)) << 4);
                ldsm_x4(aH[mf], sbAhi + off);
                ldsm_x4(aL[mf], sbAlo + off);
            }
            #pragma unroll
            for (int nf = 0; nf < 4; nf++) {
                uint32_t row = (uint32_t)(nW + nf * 8 + brow);
                uint32_t off = row * 128u + ((((uint32_t)(ks * 2 + bhalf)) ^ (row & 7u)) << 4);
                ldsm_x2(bH[nf], sbBhi + off);
                ldsm_x2(bL[nf], sbBlo + off);
            }
            #pragma unroll
            for (int mf = 0; mf < 2; mf++) if (mf < nMf)
                #pragma unroll
                for (int nf = 0; nf < 4; nf++) {
                    mma16816(acc[mf][nf], aH[mf], bH[nf]);
                    mma16816(acc[mf][nf], aL[mf], bH[nf]);
                    mma16816(acc[mf][nf], aH[mf], bL[nf]);
                }
        }

        if (it + 1 < NIT) {
            const uint32_t nb = sb + (uint32_t)((it + 1) & 1) * BUF_BYTES;
            const float sc = sRow[(it + 1) >> 1];
            #pragma unroll
            for (int q = 0; q < 8; q++)
                cvt_store(aReg[q], rbA, khA + q * 4, nb, nb + ABLK);
            #pragma unroll
            for (int q = 0; q < 4; q++) {
                float4 vb = bReg[q];
                vb.x *= sc; vb.y *= sc; vb.z *= sc; vb.w *= sc;
                cvt_store(vb, rbB, khB + q * 4, nb + 2 * ABLK, nb + 2 * ABLK + BBLK);
            }
        }
        __syncthreads();
    }

    // epilogue: silu(g)*u, col pair (2j,2j+1) = (g,u) for i = i0 + wn*16 + nf*4 + qcol
    const int qrow = lane >> 2;
    const int qcol = lane & 3;
    #pragma unroll
    for (int mf = 0; mf < 2; mf++) if (mf < nMf) {
        const int r0 = mW + mf * 16 + qrow;
        const int r1 = r0 + 8;
        #pragma unroll
        for (int nf = 0; nf < 4; nf++) {
            const int ii = i0 + wn * 16 + nf * 4 + qcol;
            float g0 = acc[mf][nf][0], u0 = acc[mf][nf][1];
            float g1 = acc[mf][nf][2], u1 = acc[mf][nf][3];
            if (r0 < mRows) {
                float s = g0 / (1.0f + __expf(-g0));
                g_hact[(size_t)(base + m0 + r0) * I_DIM + ii] = s * u0;
            }
            if (r1 < mRows) {
                float s = g1 / (1.0f + __expf(-g1));
                g_hact[(size_t)(base + m0 + r1) * I_DIM + ii] = s * u1;
            }
        }
    }
}

// ---------------------------------------------------------------------------
// Kernel 2: down-projection (bf16-split mma.sync) + routing weight scatter.
// CTA 128 x 64 H-cols. Tail M-tiles skip MMA fragments beyond mRows.
// ---------------------------------------------------------------------------
__global__ __launch_bounds__(NTHR, 2)
void gemm2_kernel(const float* __restrict__ w2, const float* __restrict__ s2,
                  const float* __restrict__ rw, float* __restrict__ out)
{
    const int e    = blockIdx.y;
    const int base = g_off[e];
    const int cntE = g_off[e + 1] - base;
    const int m0   = blockIdx.z * CTA_M;
    if (m0 >= cntE) return;
    const int mRows = min(CTA_M, cntE - m0);
    const int n0   = blockIdx.x * CTA_N;

    extern __shared__ char dsm[];
    __shared__ int spair[CTA_M];
    const uint32_t sb = (smem_u32(dsm) + 127u) & ~127u;

    const int tid  = threadIdx.x;
    const int wid  = tid >> 5;
    const int lane = tid & 31;

    if (tid < CTA_M) {
        int mm = m0 + tid;
        spair[tid] = (mm < cntE) ? g_pair[base + mm] : 0;
    }
    __syncthreads();

    const int rbA = tid >> 1;
    const int khA = (tid & 1) * 32;
    const float* aSrc = g_hact + (size_t)(base + m0 + rbA) * I_DIM + khA;
    const int rbB = tid >> 2;
    const int khB = (tid & 3) * 16;
    const float* bSrc = w2 + ((size_t)(e * H_DIM + n0 + rbB)) * I_DIM + khB;
    const float* sRow = s2 + (size_t)(e * (H_DIM / QBS) + (n0 >> 7)) * (I_DIM / QBS);

    const int wm = wid & 3, wn = wid >> 2;
    const int mW = wm * 32, nW = wn * 32;
    const int arow = lane & 15;
    const int ahalf = lane >> 4;
    const int brow = lane & 7;
    const int bhalf = (lane >> 3) & 1;

    const int nMf = (mW < mRows) ? ((mW + 16 < mRows) ? 2 : 1) : 0;

    float acc[2][4][4];
    #pragma unroll
    for (int a = 0; a < 2; a++)
        #pragma unroll
        for (int b = 0; b < 4; b++)
            #pragma unroll
            for (int c = 0; c < 4; c++) acc[a][b][c] = 0.f;

    const int NIT = I_DIM / KI;   // 16
    float4 aReg[8], bReg[4];

    {
        const float4* ap = (const float4*)aSrc;
        const float4* bp = (const float4*)bSrc;
        #pragma unroll
        for (int q = 0; q < 8; q++) aReg[q] = ap[q];
        #pragma unroll
        for (int q = 0; q < 4; q++) bReg[q] = bp[q];
        const float sc = sRow[0];
        #pragma unroll
        for (int q = 0; q < 8; q++)
            cvt_store(aReg[q], rbA, khA + q * 4, sb, sb + ABLK);
        #pragma unroll
        for (int q = 0; q < 4; q++) {
            float4 vb = bReg[q];
            vb.x *= sc; vb.y *= sc; vb.z *= sc; vb.w *= sc;
            cvt_store(vb, rbB, khB + q * 4, sb + 2 * ABLK, sb + 2 * ABLK + BBLK);
        }
    }
    __syncthreads();

    for (int it = 0; it < NIT; it++) {
        if (it + 1 < NIT) {
            const float4* ap = (const float4*)(aSrc + (it + 1) * KI);
            const float4* bp = (const float4*)(bSrc + (it + 1) * KI);
            #pragma unroll
            for (int q = 0; q < 8; q++) aReg[q] = ap[q];
            #pragma unroll
            for (int q = 0; q < 4; q++) bReg[q] = bp[q];
        }

        const uint32_t bufB = sb + (uint32_t)(it & 1) * BUF_BYTES;
        const uint32_t sbAhi = bufB, sbAlo = bufB + ABLK;
        const uint32_t sbBhi = bufB + 2 * ABLK, sbBlo = sbBhi + BBLK;

        #pragma unroll
        for (int ks = 0; ks < 4; ks++) {
            uint32_t aH[2][4], aL[2][4], bH[4][2], bL[4][2];
            #pragma unroll
            for (int mf = 0; mf < 2; mf++) if (mf < nMf) {
                uint32_t row = (uint32_t)(mW + mf * 16 + arow);
                uint32_t off = row * 128u + ((((uint32_t)(ks * 2 + ahalf)) ^ (row & 7u)) << 4);
                ldsm_x4(aH[mf], sbAhi + off);
                ldsm_x4(aL[mf], sbAlo + off);
            }
            #pragma unroll
            for (int nf = 0; nf < 4; nf++) {
                uint32_t row = (uint32_t)(nW + nf * 8 + brow);
                uint32_t off = row * 128u + ((((uint32_t)(ks * 2 + bhalf)) ^ (row & 7u)) << 4);
                ldsm_x2(bH[nf], sbBhi + off);
                ldsm_x2(bL[nf], sbBlo + off);
            }
            #pragma unroll
            for (int mf = 0; mf < 2; mf++) if (mf < nMf)
                #pragma unroll
                for (int nf = 0; nf < 4; nf++) {
                    mma16816(acc[mf][nf], aH[mf], bH[nf]);
                    mma16816(acc[mf][nf], aL[mf], bH[nf]);
                    mma16816(acc[mf][nf], aH[mf], bL[nf]);
                }
        }

        if (it + 1 < NIT) {
            const uint32_t nb = sb + (uint32_t)((it + 1) & 1) * BUF_BYTES;
            const float sc = sRow[(it + 1) >> 1];
            #pragma unroll
            for (int q = 0; q < 8; q++)
                cvt_store(aReg[q], rbA, khA + q * 4, nb, nb + ABLK);
            #pragma unroll
            for (int q = 0; q < 4; q++) {
                float4 vb = bReg[q];
                vb.x *= sc; vb.y *= sc; vb.z *= sc; vb.w *= sc;
                cvt_store(vb, rbB, khB + q * 4, nb + 2 * ABLK, nb + 2 * ABLK + BBLK);
            }
        }
        __syncthreads();
    }

    // epilogue: routing weight, scatter
    const int qrow = lane >> 2;
    const int qcol = lane & 3;
    #pragma unroll
    for (int mf = 0; mf < 2; mf++) if (mf < nMf) {
        const int r0 = mW + mf * 16 + qrow;
        const int r1 = r0 + 8;
        const int pid0 = spair[r0];
        const int pid1 = spair[r1];
        const float w0g = rw[pid0];
        const float w1g = rw[pid1];
        #pragma unroll
        for (int nf = 0; nf < 4; nf++) {
            const int col = n0 + nW + nf * 8 + qcol * 2;
            if (r0 < mRows) {
                float2 v = { acc[mf][nf][0] * w0g, acc[mf][nf][1] * w0g };
                *(float2*)&out[(size_t)pid0 * H_DIM + col] = v;
            }
            if (r1 < mRows) {
                float2 v = { acc[mf][nf][2] * w1g, acc[mf][nf][3] * w1g };
                *(float2*)&out[(size_t)pid1 * H_DIM + col] = v;
            }
        }
    }
}

// ---------------------------------------------------------------------------
// Launch
// ---------------------------------------------------------------------------
extern "C" void kernel_launch(void* const* d_in, const int* in_sizes, int n_in,
                              void* d_out, int out_size)
{
    const float* x   = (const float*)d_in[0];
    const float* w0  = (const float*)d_in[1];
    const float* w1  = (const float*)d_in[2];
    const float* w2  = (const float*)d_in[3];
    const float* s0  = (const float*)d_in[4];
    const float* s1  = (const float*)d_in[5];
    const float* s2  = (const float*)d_in[6];
    const int*   sel = (const int*)  d_in[7];
    const float* rw  = (const float*)d_in[8];
    float*       out = (float*)d_out;

    cudaFuncSetAttribute(gemm1_kernel, cudaFuncAttributeMaxDynamicSharedMemorySize, SMEM_DYN);
    cudaFuncSetAttribute(gemm2_kernel, cudaFuncAttributeMaxDynamicSharedMemorySize, SMEM_DYN);

    route_kernel<<<1, NTHR>>>(sel);

    dim3 g1(I_DIM / 32, N_EXP, N_PAIR / CTA_M);    // 32 x 16 x 16 (z early-exits)
    gemm1_kernel<<<g1, NTHR, SMEM_DYN>>>(x, w0, w1, s0, s1);

    dim3 g2(H_DIM / CTA_N, N_EXP, N_PAIR / CTA_M); // 32 x 16 x 16
    gemm2_kernel<<<g2, NTHR, SMEM_DYN>>>(w2, s2, rw, out);
}